// round 2
// baseline (speedup 1.0000x reference)
#include <cuda_runtime.h>
#include <cstdint>

#define BB 8
#define DD 8
#define KK 5
#define PP (512*1024)

// ---- scratch (device globals: no allocation allowed) ----
__device__ float g_sums[BB][KK][DD];        // per-batch per-instance channel sums
__device__ int   g_cnt[BB][KK + 1];         // per-batch per-slot pixel counts (slot 0 = bg)
__device__ float g_var[BB][KK + 1];         // per-batch per-slot variance-term sums

// ---------------------------------------------------------------------------
__global__ void init_kernel() {
    int t = threadIdx.x;
    float* s = &g_sums[0][0][0];
    for (int i = t; i < BB * KK * DD; i += blockDim.x) s[i] = 0.f;
    int* c = &g_cnt[0][0];
    for (int i = t; i < BB * (KK + 1); i += blockDim.x) c[i] = 0;
    float* v = &g_var[0][0];
    for (int i = t; i < BB * (KK + 1); i += blockDim.x) v[i] = 0.f;
}

// ---------------------------------------------------------------------------
// Pass 1: per-instance channel sums + counts for a PAIR of batch images.
// Per-thread smem slots: 6 labels x 8 floats, stride 52 floats (208B, odd # of
// 16B groups -> decorrelated bank mapping for LDS.128).
#define T1 128
#define SLOT1 52
#define GX1 296

__global__ void __launch_bounds__(T1) pass1_kernel(const float* __restrict__ emb,
                                                   const int* __restrict__ mask,
                                                   int pair) {
    __shared__ float acc[T1 * SLOT1];
    const int t = threadIdx.x;
    const int b = pair * 2 + blockIdx.y;
    float* my = acc + t * SLOT1;
#pragma unroll
    for (int j = 0; j < SLOT1; j++) my[j] = 0.f;

    unsigned long long cnt64 = 0ull;
    const float* eb = emb + (size_t)b * DD * PP;
    const int*   mb = mask + (size_t)b * PP;
    const int stride = GX1 * T1 * 4;

    for (int p0 = (blockIdx.x * T1 + t) * 4; p0 < PP; p0 += stride) {
        const int4 lab4 = *reinterpret_cast<const int4*>(mb + p0);
        float ev[4][DD];
#pragma unroll
        for (int d = 0; d < DD; d++) {
            float4 v = *reinterpret_cast<const float4*>(eb + (size_t)d * PP + p0);
            ev[0][d] = v.x; ev[1][d] = v.y; ev[2][d] = v.z; ev[3][d] = v.w;
        }
        int labs[4] = {lab4.x, lab4.y, lab4.z, lab4.w};
#pragma unroll
        for (int i = 0; i < 4; i++) {
            const int lab = labs[i];
            cnt64 += 1ull << (lab * 8);
            float* slot = my + lab * 8;
            float4 lo = *reinterpret_cast<float4*>(slot);
            float4 hi = *reinterpret_cast<float4*>(slot + 4);
            lo.x += ev[i][0]; lo.y += ev[i][1]; lo.z += ev[i][2]; lo.w += ev[i][3];
            hi.x += ev[i][4]; hi.y += ev[i][5]; hi.z += ev[i][6]; hi.w += ev[i][7];
            *reinterpret_cast<float4*>(slot)     = lo;
            *reinterpret_cast<float4*>(slot + 4) = hi;
        }
    }

    __syncthreads();
    // tree-reduce the 40 useful floats (labels 1..5) across threads
    for (int off = T1 / 2; off > 0; off >>= 1) {
        if (t < off) {
            float* a = acc + t * SLOT1;
            float* c = acc + (t + off) * SLOT1;
#pragma unroll
            for (int j = 8; j < 48; j++) a[j] += c[j];
        }
        __syncthreads();
    }
    if (t < KK * DD) atomicAdd(&g_sums[b][0][0] + t, acc[8 + t]);

    // counts: warp REDUX then per-warp atomic
#pragma unroll
    for (int k = 1; k <= KK; k++) {
        unsigned c = (unsigned)((cnt64 >> (8 * k)) & 0xffull);
        c = __reduce_add_sync(0xffffffffu, c);
        if ((t & 31) == 0) atomicAdd(&g_cnt[b][k], (int)c);
    }
}

// ---------------------------------------------------------------------------
// Pass 2: per-pixel hinge-variance term, for a PAIR of batch images.
// Centers computed inline in the block prologue from g_sums / g_cnt.
#define T2 256
#define VSLOT 9
#define GX2 296

__device__ __forceinline__ float fsqrt_approx(float x) {
    float r;
    asm("sqrt.approx.f32 %0, %1;" : "=f"(r) : "f"(x));
    return r;
}

__global__ void __launch_bounds__(T2) pass2_kernel(const float* __restrict__ emb,
                                                   const int* __restrict__ mask,
                                                   int pair) {
    __shared__ float4 cs4[(KK + 1) * 2];   // centers table, float4-aligned
    __shared__ float vacc[T2 * VSLOT];
    const int t = threadIdx.x;
    const int b = pair * 2 + blockIdx.y;

    if (t < (KK + 1) * DD) {
        const int slot = t / DD, d = t % DD;
        float v = 0.f;
        if (slot >= 1)
            v = g_sums[b][slot - 1][d] / fmaxf((float)g_cnt[b][slot], 1.f);
        reinterpret_cast<float*>(cs4)[t] = v;
    }
#pragma unroll
    for (int j = 0; j < VSLOT; j++) vacc[t * VSLOT + j] = 0.f;
    __syncthreads();

    const float* eb = emb + (size_t)b * DD * PP;
    const int*   mb = mask + (size_t)b * PP;
    const int stride = GX2 * T2 * 4;

    for (int p0 = (blockIdx.x * T2 + t) * 4; p0 < PP; p0 += stride) {
        const int4 lab4 = *reinterpret_cast<const int4*>(mb + p0);
        float ev[4][DD];
#pragma unroll
        for (int d = 0; d < DD; d++) {
            float4 v = *reinterpret_cast<const float4*>(eb + (size_t)d * PP + p0);
            ev[0][d] = v.x; ev[1][d] = v.y; ev[2][d] = v.z; ev[3][d] = v.w;
        }
        int labs[4] = {lab4.x, lab4.y, lab4.z, lab4.w};
#pragma unroll
        for (int i = 0; i < 4; i++) {
            const int lab = labs[i];
            const float4 clo = cs4[lab * 2];
            const float4 chi = cs4[lab * 2 + 1];
            float d0 = ev[i][0] - clo.x;
            float s  = d0 * d0;
            float d1 = ev[i][1] - clo.y; s = fmaf(d1, d1, s);
            float d2 = ev[i][2] - clo.z; s = fmaf(d2, d2, s);
            float d3 = ev[i][3] - clo.w; s = fmaf(d3, d3, s);
            float d4 = ev[i][4] - chi.x; s = fmaf(d4, d4, s);
            float d5 = ev[i][5] - chi.y; s = fmaf(d5, d5, s);
            float d6 = ev[i][6] - chi.z; s = fmaf(d6, d6, s);
            float d7 = ev[i][7] - chi.w; s = fmaf(d7, d7, s);
            // max(sqrt(s)-0.5,0)^2 == s - sqrt(s) + 0.25 when s > 0.25 else 0
            float val = (s - fsqrt_approx(s)) + 0.25f;
            val = (s > 0.25f) ? val : 0.f;
            vacc[t * VSLOT + lab] += val;
        }
    }

    __syncthreads();
    for (int off = T2 / 2; off > 0; off >>= 1) {
        if (t < off) {
            float* a = vacc + t * VSLOT;
            float* c = vacc + (t + off) * VSLOT;
#pragma unroll
            for (int j = 0; j < 6; j++) a[j] += c[j];
        }
        __syncthreads();
    }
    if (t >= 1 && t <= KK) atomicAdd(&g_var[b][t], vacc[t]);
}

// ---------------------------------------------------------------------------
__global__ void finalize_kernel(float* __restrict__ out) {
    __shared__ float s_var[BB], s_dist[BB], s_reg[BB], s_has[BB];
    const int t = threadIdx.x;
    if (t < BB) {
        const int b = t;
        float cnt[KK], present[KK], N = 0.f;
        float ctr[KK][DD];
#pragma unroll
        for (int k = 0; k < KK; k++) {
            cnt[k] = (float)g_cnt[b][k + 1];
            present[k] = cnt[k] > 0.f ? 1.f : 0.f;
            N += present[k];
            const float inv = 1.f / fmaxf(cnt[k], 1.f);
#pragma unroll
            for (int d = 0; d < DD; d++) ctr[k][d] = g_sums[b][k][d] * inv;
        }
        // variance loss
        float lv = 0.f;
#pragma unroll
        for (int k = 0; k < KK; k++)
            lv += present[k] * (g_var[b][k + 1] / fmaxf(cnt[k], 1.f));
        lv /= fmaxf(N, 1.f);
        // distance loss
        float ld = 0.f;
        for (int i = 0; i < KK; i++) {
            for (int j = i + 1; j < KK; j++) {
                if (present[i] > 0.f && present[j] > 0.f) {
                    float dsq = 0.f;
#pragma unroll
                    for (int d = 0; d < DD; d++) {
                        float df = ctr[i][d] - ctr[j][d];
                        dsq = fmaf(df, df, dsq);
                    }
                    float dist = sqrtf(dsq);
                    float term = fmaxf(6.0f - dist, 0.f);  // 2*DELTA_D = 6
                    ld += term * term;
                }
            }
        }
        float npairs = N * (N - 1.f) * 0.5f;
        ld /= (N > 1.f) ? npairs : 1.f;
        // regularization
        float lr = 0.f;
#pragma unroll
        for (int k = 0; k < KK; k++) {
            if (present[k] > 0.f) {
                float nsq = 0.f;
#pragma unroll
                for (int d = 0; d < DD; d++) {
                    float c = ctr[k][d];
                    nsq = fmaf(c, c, nsq);
                }
                lr += sqrtf(nsq);
            }
        }
        lr /= fmaxf(N, 1.f);
        s_var[b] = lv; s_dist[b] = ld; s_reg[b] = lr;
        s_has[b] = (N > 0.f) ? 1.f : 0.f;
    }
    __syncthreads();
    if (t == 0) {
        float hv = 0.f, hd = 0.f, hr = 0.f, hh = 0.f;
#pragma unroll
        for (int b = 0; b < BB; b++) {
            hh += s_has[b];
            hv += s_var[b] * s_has[b];
            hd += s_dist[b] * s_has[b];
            hr += s_reg[b] * s_has[b];
        }
        const float den = fmaxf(hh, 1.f);
        const float var = hv / den, dist = hd / den, reg = hr / den;
        out[0] = var + dist + 0.001f * reg;  // ALPHA=BETA=1, GAMMA=0.001
        out[1] = var;
        out[2] = dist;
        out[3] = reg;
    }
}

// ---------------------------------------------------------------------------
extern "C" void kernel_launch(void* const* d_in, const int* in_sizes, int n_in,
                              void* d_out, int out_size) {
    const float* emb  = (const float*)d_in[0];
    const int*   mask = (const int*)d_in[1];
    float*       out  = (float*)d_out;

    init_kernel<<<1, 256>>>();
    for (int pair = 0; pair < 4; pair++) {
        dim3 g1(GX1, 2);
        pass1_kernel<<<g1, T1>>>(emb, mask, pair);
        dim3 g2(GX2, 2);
        pass2_kernel<<<g2, T2>>>(emb, mask, pair);
    }
    finalize_kernel<<<1, 32>>>(out);
}

// round 3
// speedup vs baseline: 1.1818x; 1.1818x over previous
#include <cuda_runtime.h>
#include <cstdint>

#define BB 8
#define DD 8
#define KK 5
#define PP (512*1024)

// ---- scratch (device globals: no allocation allowed) ----
__device__ float g_sums[BB][KK][DD];        // per-batch per-instance channel sums
__device__ int   g_cnt[BB][KK + 1];         // per-batch per-slot pixel counts (slot 0 = bg)
__device__ float g_var[BB][KK + 1];         // per-batch per-slot variance-term sums

// ---------------------------------------------------------------------------
__global__ void init_kernel() {
    int t = threadIdx.x;
    float* s = &g_sums[0][0][0];
    for (int i = t; i < BB * KK * DD; i += blockDim.x) s[i] = 0.f;
    int* c = &g_cnt[0][0];
    for (int i = t; i < BB * (KK + 1); i += blockDim.x) c[i] = 0;
    float* v = &g_var[0][0];
    for (int i = t; i < BB * (KK + 1); i += blockDim.x) v[i] = 0.f;
}

// ---------------------------------------------------------------------------
// Pass 1: per-instance channel sums + counts. Register accumulators,
// branchless masked FFMA. Exactly 2 iterations per thread.
#define T1 256
#define GX1 256

__global__ void __launch_bounds__(T1) pass1_kernel(const float* __restrict__ emb,
                                                   const int* __restrict__ mask) {
    const int t = threadIdx.x;
    const int b = blockIdx.y;
    const int w = t >> 5, lane = t & 31;

    float acc[KK][DD];
#pragma unroll
    for (int k = 0; k < KK; k++)
#pragma unroll
        for (int d = 0; d < DD; d++) acc[k][d] = 0.f;
    unsigned long long cnt64 = 0ull;

    const float* eb = emb + (size_t)b * DD * PP;
    const int*   mb = mask + (size_t)b * PP;
    const int base = (blockIdx.x * T1 + t) * 4;
    const int stride = GX1 * T1 * 4;   // PP / stride == 2 exactly

#pragma unroll
    for (int it = 0; it < 2; it++) {
        const int p0 = base + it * stride;
        const int4 lab4 = *reinterpret_cast<const int4*>(mb + p0);
        float ev[4][DD];
#pragma unroll
        for (int d = 0; d < DD; d++) {
            float4 v = *reinterpret_cast<const float4*>(eb + (size_t)d * PP + p0);
            ev[0][d] = v.x; ev[1][d] = v.y; ev[2][d] = v.z; ev[3][d] = v.w;
        }
        int labs[4] = {lab4.x, lab4.y, lab4.z, lab4.w};
#pragma unroll
        for (int i = 0; i < 4; i++) {
            const int lab = labs[i];
            cnt64 += 1ull << (lab * 8);
#pragma unroll
            for (int k = 0; k < KK; k++) {
                const float m = (lab == k + 1) ? 1.f : 0.f;
#pragma unroll
                for (int d = 0; d < DD; d++)
                    acc[k][d] = fmaf(m, ev[i][d], acc[k][d]);
            }
        }
    }

    // warp-shuffle reduce the 40 accumulators
#pragma unroll
    for (int off = 16; off > 0; off >>= 1) {
#pragma unroll
        for (int k = 0; k < KK; k++)
#pragma unroll
            for (int d = 0; d < DD; d++)
                acc[k][d] += __shfl_down_sync(0xffffffffu, acc[k][d], off);
    }

    __shared__ float red[(T1 / 32)][KK * DD];
    if (lane == 0) {
#pragma unroll
        for (int k = 0; k < KK; k++)
#pragma unroll
            for (int d = 0; d < DD; d++)
                red[w][k * DD + d] = acc[k][d];
    }
    __syncthreads();
    if (t < KK * DD) {
        float s = 0.f;
#pragma unroll
        for (int ww = 0; ww < T1 / 32; ww++) s += red[ww][t];
        atomicAdd(&g_sums[b][0][0] + t, s);
    }

    // counts: warp REDUX then per-warp atomic
#pragma unroll
    for (int k = 1; k <= KK; k++) {
        unsigned c = (unsigned)((cnt64 >> (8 * k)) & 0xffull);
        c = __reduce_add_sync(0xffffffffu, c);
        if (lane == 0) atomicAdd(&g_cnt[b][k], (int)c);
    }
}

// ---------------------------------------------------------------------------
// Pass 2: per-pixel hinge-variance term. Centers computed inline in the block
// prologue; register accumulators + masked FFMA; exactly 2 iterations/thread.
#define T2 256
#define GX2 256

__device__ __forceinline__ float fsqrt_approx(float x) {
    float r;
    asm("sqrt.approx.f32 %0, %1;" : "=f"(r) : "f"(x));
    return r;
}

__global__ void __launch_bounds__(T2) pass2_kernel(const float* __restrict__ emb,
                                                   const int* __restrict__ mask) {
    __shared__ float4 cs4[(KK + 1) * 2];   // centers table, float4-aligned
    const int t = threadIdx.x;
    const int b = blockIdx.y;
    const int w = t >> 5, lane = t & 31;

    if (t < (KK + 1) * DD) {
        const int slot = t / DD, d = t % DD;
        float v = 0.f;
        if (slot >= 1)
            v = g_sums[b][slot - 1][d] / fmaxf((float)g_cnt[b][slot], 1.f);
        reinterpret_cast<float*>(cs4)[t] = v;
    }
    __syncthreads();

    float vacc[KK];
#pragma unroll
    for (int k = 0; k < KK; k++) vacc[k] = 0.f;

    const float* eb = emb + (size_t)b * DD * PP;
    const int*   mb = mask + (size_t)b * PP;
    const int base = (blockIdx.x * T2 + t) * 4;
    const int stride = GX2 * T2 * 4;   // PP / stride == 2 exactly

#pragma unroll
    for (int it = 0; it < 2; it++) {
        const int p0 = base + it * stride;
        const int4 lab4 = *reinterpret_cast<const int4*>(mb + p0);
        float ev[4][DD];
#pragma unroll
        for (int d = 0; d < DD; d++) {
            float4 v = *reinterpret_cast<const float4*>(eb + (size_t)d * PP + p0);
            ev[0][d] = v.x; ev[1][d] = v.y; ev[2][d] = v.z; ev[3][d] = v.w;
        }
        int labs[4] = {lab4.x, lab4.y, lab4.z, lab4.w};
#pragma unroll
        for (int i = 0; i < 4; i++) {
            const int lab = labs[i];
            const float4 clo = cs4[lab * 2];
            const float4 chi = cs4[lab * 2 + 1];
            float d0 = ev[i][0] - clo.x;
            float s  = d0 * d0;
            float d1 = ev[i][1] - clo.y; s = fmaf(d1, d1, s);
            float d2 = ev[i][2] - clo.z; s = fmaf(d2, d2, s);
            float d3 = ev[i][3] - clo.w; s = fmaf(d3, d3, s);
            float d4 = ev[i][4] - chi.x; s = fmaf(d4, d4, s);
            float d5 = ev[i][5] - chi.y; s = fmaf(d5, d5, s);
            float d6 = ev[i][6] - chi.z; s = fmaf(d6, d6, s);
            float d7 = ev[i][7] - chi.w; s = fmaf(d7, d7, s);
            // max(sqrt(s)-0.5,0)^2 == s - sqrt(s) + 0.25 when s > 0.25 else 0
            float val = (s - fsqrt_approx(s)) + 0.25f;
            val = (s > 0.25f) ? val : 0.f;
#pragma unroll
            for (int k = 0; k < KK; k++) {
                const float m = (lab == k + 1) ? 1.f : 0.f;
                vacc[k] = fmaf(m, val, vacc[k]);
            }
        }
    }

    // warp-shuffle reduce the 5 accumulators, then per-warp atomics
#pragma unroll
    for (int off = 16; off > 0; off >>= 1) {
#pragma unroll
        for (int k = 0; k < KK; k++)
            vacc[k] += __shfl_down_sync(0xffffffffu, vacc[k], off);
    }
    __shared__ float red[(T2 / 32)][KK];
    if (lane == 0) {
#pragma unroll
        for (int k = 0; k < KK; k++) red[w][k] = vacc[k];
    }
    __syncthreads();
    if (t < KK) {
        float s = 0.f;
#pragma unroll
        for (int ww = 0; ww < T2 / 32; ww++) s += red[ww][t];
        atomicAdd(&g_var[b][t + 1], s);
    }
}

// ---------------------------------------------------------------------------
__global__ void finalize_kernel(float* __restrict__ out) {
    __shared__ float s_var[BB], s_dist[BB], s_reg[BB], s_has[BB];
    const int t = threadIdx.x;
    if (t < BB) {
        const int b = t;
        float cnt[KK], present[KK], N = 0.f;
        float ctr[KK][DD];
#pragma unroll
        for (int k = 0; k < KK; k++) {
            cnt[k] = (float)g_cnt[b][k + 1];
            present[k] = cnt[k] > 0.f ? 1.f : 0.f;
            N += present[k];
            const float inv = 1.f / fmaxf(cnt[k], 1.f);
#pragma unroll
            for (int d = 0; d < DD; d++) ctr[k][d] = g_sums[b][k][d] * inv;
        }
        // variance loss
        float lv = 0.f;
#pragma unroll
        for (int k = 0; k < KK; k++)
            lv += present[k] * (g_var[b][k + 1] / fmaxf(cnt[k], 1.f));
        lv /= fmaxf(N, 1.f);
        // distance loss
        float ld = 0.f;
        for (int i = 0; i < KK; i++) {
            for (int j = i + 1; j < KK; j++) {
                if (present[i] > 0.f && present[j] > 0.f) {
                    float dsq = 0.f;
#pragma unroll
                    for (int d = 0; d < DD; d++) {
                        float df = ctr[i][d] - ctr[j][d];
                        dsq = fmaf(df, df, dsq);
                    }
                    float dist = sqrtf(dsq);
                    float term = fmaxf(6.0f - dist, 0.f);  // 2*DELTA_D = 6
                    ld += term * term;
                }
            }
        }
        float npairs = N * (N - 1.f) * 0.5f;
        ld /= (N > 1.f) ? npairs : 1.f;
        // regularization
        float lr = 0.f;
#pragma unroll
        for (int k = 0; k < KK; k++) {
            if (present[k] > 0.f) {
                float nsq = 0.f;
#pragma unroll
                for (int d = 0; d < DD; d++) {
                    float c = ctr[k][d];
                    nsq = fmaf(c, c, nsq);
                }
                lr += sqrtf(nsq);
            }
        }
        lr /= fmaxf(N, 1.f);
        s_var[b] = lv; s_dist[b] = ld; s_reg[b] = lr;
        s_has[b] = (N > 0.f) ? 1.f : 0.f;
    }
    __syncthreads();
    if (t == 0) {
        float hv = 0.f, hd = 0.f, hr = 0.f, hh = 0.f;
#pragma unroll
        for (int b = 0; b < BB; b++) {
            hh += s_has[b];
            hv += s_var[b] * s_has[b];
            hd += s_dist[b] * s_has[b];
            hr += s_reg[b] * s_has[b];
        }
        const float den = fmaxf(hh, 1.f);
        const float var = hv / den, dist = hd / den, reg = hr / den;
        out[0] = var + dist + 0.001f * reg;  // ALPHA=BETA=1, GAMMA=0.001
        out[1] = var;
        out[2] = dist;
        out[3] = reg;
    }
}

// ---------------------------------------------------------------------------
extern "C" void kernel_launch(void* const* d_in, const int* in_sizes, int n_in,
                              void* d_out, int out_size) {
    const float* emb  = (const float*)d_in[0];
    const int*   mask = (const int*)d_in[1];
    float*       out  = (float*)d_out;

    init_kernel<<<1, 256>>>();
    dim3 g1(GX1, BB);
    pass1_kernel<<<g1, T1>>>(emb, mask);
    dim3 g2(GX2, BB);
    pass2_kernel<<<g2, T2>>>(emb, mask);
    finalize_kernel<<<1, 32>>>(out);
}

// round 4
// speedup vs baseline: 1.2342x; 1.0444x over previous
#include <cuda_runtime.h>
#include <cstdint>

#define BB 8
#define DD 8
#define KK 5
#define PP (512*1024)

// ---- scratch (device globals; zero-initialized at module load, and reset by
// the finalizing block at the end of every run so graph replays start clean) ----
__device__ float    g_sums[BB][KK][DD];   // per-batch per-instance channel sums
__device__ int      g_cnt[BB][KK + 1];    // per-batch per-slot pixel counts
__device__ float    g_var[BB][KK + 1];    // per-batch per-slot variance sums
__device__ unsigned g_done;               // pass2 block completion counter

// ---------------------------------------------------------------------------
// Pass 1: per-instance channel sums + counts. Register accumulators,
// branchless masked FFMA. T=128 keeps occupancy high despite ~90 regs.
#define T1 128
#define GX1 512

__global__ void __launch_bounds__(T1) pass1_kernel(const float* __restrict__ emb,
                                                   const int* __restrict__ mask) {
    const int t = threadIdx.x;
    const int b = blockIdx.y;
    const int w = t >> 5, lane = t & 31;

    float acc[KK][DD];
#pragma unroll
    for (int k = 0; k < KK; k++)
#pragma unroll
        for (int d = 0; d < DD; d++) acc[k][d] = 0.f;
    unsigned long long cnt64 = 0ull;

    const float* eb = emb + (size_t)b * DD * PP;
    const int*   mb = mask + (size_t)b * PP;
    const int base = (blockIdx.x * T1 + t) * 4;
    const int stride = GX1 * T1 * 4;   // PP / stride == 2 exactly

#pragma unroll
    for (int it = 0; it < 2; it++) {
        const int p0 = base + it * stride;
        const int4 lab4 = *reinterpret_cast<const int4*>(mb + p0);
        float ev[4][DD];
#pragma unroll
        for (int d = 0; d < DD; d++) {
            float4 v = *reinterpret_cast<const float4*>(eb + (size_t)d * PP + p0);
            ev[0][d] = v.x; ev[1][d] = v.y; ev[2][d] = v.z; ev[3][d] = v.w;
        }
        int labs[4] = {lab4.x, lab4.y, lab4.z, lab4.w};
#pragma unroll
        for (int i = 0; i < 4; i++) {
            const int lab = labs[i];
            cnt64 += 1ull << (lab * 8);
#pragma unroll
            for (int k = 0; k < KK; k++) {
                const float m = (lab == k + 1) ? 1.f : 0.f;
#pragma unroll
                for (int d = 0; d < DD; d++)
                    acc[k][d] = fmaf(m, ev[i][d], acc[k][d]);
            }
        }
    }

    // warp-shuffle reduce the 40 accumulators
#pragma unroll
    for (int off = 16; off > 0; off >>= 1) {
#pragma unroll
        for (int k = 0; k < KK; k++)
#pragma unroll
            for (int d = 0; d < DD; d++)
                acc[k][d] += __shfl_down_sync(0xffffffffu, acc[k][d], off);
    }

    __shared__ float red[(T1 / 32)][KK * DD];
    if (lane == 0) {
#pragma unroll
        for (int k = 0; k < KK; k++)
#pragma unroll
            for (int d = 0; d < DD; d++)
                red[w][k * DD + d] = acc[k][d];
    }
    __syncthreads();
    if (t < KK * DD) {
        float s = 0.f;
#pragma unroll
        for (int ww = 0; ww < T1 / 32; ww++) s += red[ww][t];
        atomicAdd(&g_sums[b][0][0] + t, s);
    }

#pragma unroll
    for (int k = 1; k <= KK; k++) {
        unsigned c = (unsigned)((cnt64 >> (8 * k)) & 0xffull);
        c = __reduce_add_sync(0xffffffffu, c);
        if (lane == 0) atomicAdd(&g_cnt[b][k], (int)c);
    }
}

// ---------------------------------------------------------------------------
// Pass 2: per-pixel hinge-variance term (centers inline in prologue), with the
// last-finishing block doing the full loss finalization and scratch reset.
#define T2 256
#define GX2 256
#define P2_BLOCKS (GX2 * BB)

__device__ __forceinline__ float fsqrt_approx(float x) {
    float r;
    asm("sqrt.approx.f32 %0, %1;" : "=f"(r) : "f"(x));
    return r;
}

__global__ void __launch_bounds__(T2) pass2_kernel(const float* __restrict__ emb,
                                                   const int* __restrict__ mask,
                                                   float* __restrict__ out) {
    __shared__ float4 cs4[(KK + 1) * 2];   // centers table, float4-aligned
    __shared__ bool s_last;
    const int t = threadIdx.x;
    const int b = blockIdx.y;
    const int w = t >> 5, lane = t & 31;

    if (t < (KK + 1) * DD) {
        const int slot = t / DD, d = t % DD;
        float v = 0.f;
        if (slot >= 1)
            v = g_sums[b][slot - 1][d] / fmaxf((float)g_cnt[b][slot], 1.f);
        reinterpret_cast<float*>(cs4)[t] = v;
    }
    __syncthreads();

    float vacc[KK];
#pragma unroll
    for (int k = 0; k < KK; k++) vacc[k] = 0.f;

    const float* eb = emb + (size_t)b * DD * PP;
    const int*   mb = mask + (size_t)b * PP;
    const int base = (blockIdx.x * T2 + t) * 4;
    const int stride = GX2 * T2 * 4;   // PP / stride == 2 exactly

#pragma unroll
    for (int it = 0; it < 2; it++) {
        const int p0 = base + it * stride;
        const int4 lab4 = *reinterpret_cast<const int4*>(mb + p0);
        float ev[4][DD];
#pragma unroll
        for (int d = 0; d < DD; d++) {
            float4 v = *reinterpret_cast<const float4*>(eb + (size_t)d * PP + p0);
            ev[0][d] = v.x; ev[1][d] = v.y; ev[2][d] = v.z; ev[3][d] = v.w;
        }
        int labs[4] = {lab4.x, lab4.y, lab4.z, lab4.w};
#pragma unroll
        for (int i = 0; i < 4; i++) {
            const int lab = labs[i];
            const float4 clo = cs4[lab * 2];
            const float4 chi = cs4[lab * 2 + 1];
            float d0 = ev[i][0] - clo.x;
            float s  = d0 * d0;
            float d1 = ev[i][1] - clo.y; s = fmaf(d1, d1, s);
            float d2 = ev[i][2] - clo.z; s = fmaf(d2, d2, s);
            float d3 = ev[i][3] - clo.w; s = fmaf(d3, d3, s);
            float d4 = ev[i][4] - chi.x; s = fmaf(d4, d4, s);
            float d5 = ev[i][5] - chi.y; s = fmaf(d5, d5, s);
            float d6 = ev[i][6] - chi.z; s = fmaf(d6, d6, s);
            float d7 = ev[i][7] - chi.w; s = fmaf(d7, d7, s);
            // max(sqrt(s)-0.5,0)^2 == s - sqrt(s) + 0.25 when s > 0.25 else 0
            float val = (s - fsqrt_approx(s)) + 0.25f;
            val = (s > 0.25f) ? val : 0.f;
#pragma unroll
            for (int k = 0; k < KK; k++) {
                const float m = (lab == k + 1) ? 1.f : 0.f;
                vacc[k] = fmaf(m, val, vacc[k]);
            }
        }
    }

#pragma unroll
    for (int off = 16; off > 0; off >>= 1) {
#pragma unroll
        for (int k = 0; k < KK; k++)
            vacc[k] += __shfl_down_sync(0xffffffffu, vacc[k], off);
    }
    __shared__ float red[(T2 / 32)][KK];
    if (lane == 0) {
#pragma unroll
        for (int k = 0; k < KK; k++) red[w][k] = vacc[k];
    }
    __syncthreads();
    if (t < KK) {
        float s = 0.f;
#pragma unroll
        for (int ww = 0; ww < T2 / 32; ww++) s += red[ww][t];
        atomicAdd(&g_var[b][t + 1], s);
    }

    // ---- last-block finalize + scratch reset ----
    __threadfence();
    __syncthreads();
    if (t == 0) {
        unsigned old = atomicAdd(&g_done, 1u);
        s_last = (old == (unsigned)(P2_BLOCKS - 1));
    }
    __syncthreads();
    if (!s_last) return;

    __shared__ float s_var[BB], s_dist[BB], s_reg[BB], s_has[BB];
    if (t < BB) {
        const int bb = t;
        float cnt[KK], present[KK], N = 0.f;
        float ctr[KK][DD];
#pragma unroll
        for (int k = 0; k < KK; k++) {
            cnt[k] = (float)g_cnt[bb][k + 1];
            present[k] = cnt[k] > 0.f ? 1.f : 0.f;
            N += present[k];
            const float inv = 1.f / fmaxf(cnt[k], 1.f);
#pragma unroll
            for (int d = 0; d < DD; d++) ctr[k][d] = g_sums[bb][k][d] * inv;
        }
        float lv = 0.f;
#pragma unroll
        for (int k = 0; k < KK; k++)
            lv += present[k] * (g_var[bb][k + 1] / fmaxf(cnt[k], 1.f));
        lv /= fmaxf(N, 1.f);

        float ld = 0.f;
        for (int i = 0; i < KK; i++) {
            for (int j = i + 1; j < KK; j++) {
                if (present[i] > 0.f && present[j] > 0.f) {
                    float dsq = 0.f;
#pragma unroll
                    for (int d = 0; d < DD; d++) {
                        float df = ctr[i][d] - ctr[j][d];
                        dsq = fmaf(df, df, dsq);
                    }
                    float dist = sqrtf(dsq);
                    float term = fmaxf(6.0f - dist, 0.f);  // 2*DELTA_D = 6
                    ld += term * term;
                }
            }
        }
        float npairs = N * (N - 1.f) * 0.5f;
        ld /= (N > 1.f) ? npairs : 1.f;

        float lr = 0.f;
#pragma unroll
        for (int k = 0; k < KK; k++) {
            if (present[k] > 0.f) {
                float nsq = 0.f;
#pragma unroll
                for (int d = 0; d < DD; d++) {
                    float c = ctr[k][d];
                    nsq = fmaf(c, c, nsq);
                }
                lr += sqrtf(nsq);
            }
        }
        lr /= fmaxf(N, 1.f);
        s_var[bb] = lv; s_dist[bb] = ld; s_reg[bb] = lr;
        s_has[bb] = (N > 0.f) ? 1.f : 0.f;
    }
    __syncthreads();
    if (t == 0) {
        float hv = 0.f, hd = 0.f, hr = 0.f, hh = 0.f;
#pragma unroll
        for (int bb = 0; bb < BB; bb++) {
            hh += s_has[bb];
            hv += s_var[bb] * s_has[bb];
            hd += s_dist[bb] * s_has[bb];
            hr += s_reg[bb] * s_has[bb];
        }
        const float den = fmaxf(hh, 1.f);
        const float var = hv / den, dist = hd / den, reg = hr / den;
        out[0] = var + dist + 0.001f * reg;  // ALPHA=BETA=1, GAMMA=0.001
        out[1] = var;
        out[2] = dist;
        out[3] = reg;
    }

    // reset all scratch for the next graph replay
    {
        float* s = &g_sums[0][0][0];
        for (int i = t; i < BB * KK * DD; i += T2) s[i] = 0.f;
        int* c = &g_cnt[0][0];
        for (int i = t; i < BB * (KK + 1); i += T2) c[i] = 0;
        float* v = &g_var[0][0];
        for (int i = t; i < BB * (KK + 1); i += T2) v[i] = 0.f;
        if (t == 0) g_done = 0u;
    }
}

// ---------------------------------------------------------------------------
extern "C" void kernel_launch(void* const* d_in, const int* in_sizes, int n_in,
                              void* d_out, int out_size) {
    const float* emb  = (const float*)d_in[0];
    const int*   mask = (const int*)d_in[1];
    float*       out  = (float*)d_out;

    dim3 g1(GX1, BB);
    pass1_kernel<<<g1, T1>>>(emb, mask);
    dim3 g2(GX2, BB);
    pass2_kernel<<<g2, T2>>>(emb, mask, out);
}

// round 6
// speedup vs baseline: 1.6289x; 1.3198x over previous
#include <cuda_runtime.h>
#include <cstdint>

#define BB 8
#define DD 8
#define KK 5
#define PP (512*1024)

// ---- scratch (device globals; zero-initialized at module load; finalize
// resets them at the end of every run so graph replays start clean) ----
__device__ float g_sums[BB][KK][DD];   // per-batch per-instance channel sums
__device__ int   g_cnt[BB][KK + 1];    // per-batch per-slot pixel counts
__device__ float g_var[BB][KK + 1];    // per-batch per-slot variance sums

// ---------------------------------------------------------------------------
// Pass 1: per-instance channel sums + counts.
// Lane-split: even lanes accumulate channels 0-3, odd lanes channels 4-7;
// a lane pair shares the same 4 pixels (the int4 mask load coalesces).
// acc = 5x4 regs per thread -> ~60 regs total -> high occupancy.
#define T1 128
#define GX1 256
// coverage per iter: GX1 * (T1/2) * 4 px = 65536 -> 8 iters

__global__ void __launch_bounds__(T1) pass1_kernel(const float* __restrict__ emb,
                                                   const int* __restrict__ mask) {
    const int t = threadIdx.x;
    const int b = blockIdx.y;
    const int w = t >> 5, lane = t & 31;
    const int half = lane & 1;             // 0: ch0-3, 1: ch4-7

    float acc[KK][4];
#pragma unroll
    for (int k = 0; k < KK; k++)
#pragma unroll
        for (int j = 0; j < 4; j++) acc[k][j] = 0.f;
    unsigned long long cnt64 = 0ull;

    const float* eb = emb + (size_t)b * DD * PP + (size_t)(half * 4) * PP;
    const int*   mb = mask + (size_t)b * PP;
    int p = (blockIdx.x * (T1 / 2) + (t >> 1)) * 4;
    const int stride = GX1 * (T1 / 2) * 4;

#pragma unroll
    for (int it = 0; it < 8; it++, p += stride) {
        const int4 lab4 = *reinterpret_cast<const int4*>(mb + p);
        const float4 v0 = *reinterpret_cast<const float4*>(eb + 0 * (size_t)PP + p);
        const float4 v1 = *reinterpret_cast<const float4*>(eb + 1 * (size_t)PP + p);
        const float4 v2 = *reinterpret_cast<const float4*>(eb + 2 * (size_t)PP + p);
        const float4 v3 = *reinterpret_cast<const float4*>(eb + 3 * (size_t)PP + p);
        const float ev[4][4] = {
            {v0.x, v1.x, v2.x, v3.x},
            {v0.y, v1.y, v2.y, v3.y},
            {v0.z, v1.z, v2.z, v3.z},
            {v0.w, v1.w, v2.w, v3.w}};
        const int labs[4] = {lab4.x, lab4.y, lab4.z, lab4.w};
#pragma unroll
        for (int i = 0; i < 4; i++) {
            const int lab = labs[i];
            cnt64 += 1ull << (lab * 8);
#pragma unroll
            for (int k = 0; k < KK; k++) {
                const float m = (lab == k + 1) ? 1.f : 0.f;
#pragma unroll
                for (int j = 0; j < 4; j++)
                    acc[k][j] = fmaf(m, ev[i][j], acc[k][j]);
            }
        }
    }

    // parity-preserving warp reduction (offsets 16..2): lane0 = even-lane sums
    // (channels 0-3), lane1 = odd-lane sums (channels 4-7)
#pragma unroll
    for (int off = 16; off >= 2; off >>= 1) {
#pragma unroll
        for (int k = 0; k < KK; k++)
#pragma unroll
            for (int j = 0; j < 4; j++)
                acc[k][j] += __shfl_down_sync(0xffffffffu, acc[k][j], off);
    }

    __shared__ float red[T1 / 32][KK][DD];
    if (lane < 2) {
#pragma unroll
        for (int k = 0; k < KK; k++)
#pragma unroll
            for (int j = 0; j < 4; j++)
                red[w][k][half * 4 + j] = acc[k][j];
    }
    __syncthreads();
    if (t < KK * DD) {
        float s = 0.f;
#pragma unroll
        for (int ww = 0; ww < T1 / 32; ww++) s += (&red[ww][0][0])[t];
        atomicAdd(&g_sums[b][0][0] + t, s);
    }

    // counts: every pixel was counted by BOTH parity lanes -> halve
#pragma unroll
    for (int k = 1; k <= KK; k++) {
        unsigned c = (unsigned)((cnt64 >> (8 * k)) & 0xffull);
        c = __reduce_add_sync(0xffffffffu, c);
        if (lane == 0) atomicAdd(&g_cnt[b][k], (int)(c >> 1));
    }
}

// ---------------------------------------------------------------------------
// Pass 2: per-pixel hinge-variance term (round-1 proven shape: smem per-thread
// slots for the 6 label accumulators), centers computed inline in prologue.
#define T2 256
#define VSLOT 9
#define GX2 128

__device__ __forceinline__ float fsqrt_approx(float x) {
    float r;
    asm("sqrt.approx.f32 %0, %1;" : "=f"(r) : "f"(x));
    return r;
}

__global__ void __launch_bounds__(T2) pass2_kernel(const float* __restrict__ emb,
                                                   const int* __restrict__ mask) {
    __shared__ float4 cs4[(KK + 1) * 2];   // centers table, float4-aligned
    __shared__ float vacc[T2 * VSLOT];
    const int t = threadIdx.x;
    const int b = blockIdx.y;

    if (t < (KK + 1) * DD) {
        const int slot = t / DD, d = t % DD;
        float v = 0.f;
        if (slot >= 1)
            v = g_sums[b][slot - 1][d] / fmaxf((float)g_cnt[b][slot], 1.f);
        reinterpret_cast<float*>(cs4)[t] = v;
    }
#pragma unroll
    for (int j = 0; j < VSLOT; j++) vacc[t * VSLOT + j] = 0.f;
    __syncthreads();

    const float* eb = emb + (size_t)b * DD * PP;
    const int*   mb = mask + (size_t)b * PP;
    const int stride = GX2 * T2 * 4;

    for (int p0 = (blockIdx.x * T2 + t) * 4; p0 < PP; p0 += stride) {
        const int4 lab4 = *reinterpret_cast<const int4*>(mb + p0);
        float ev[4][DD];
#pragma unroll
        for (int d = 0; d < DD; d++) {
            float4 v = *reinterpret_cast<const float4*>(eb + (size_t)d * PP + p0);
            ev[0][d] = v.x; ev[1][d] = v.y; ev[2][d] = v.z; ev[3][d] = v.w;
        }
        int labs[4] = {lab4.x, lab4.y, lab4.z, lab4.w};
#pragma unroll
        for (int i = 0; i < 4; i++) {
            const int lab = labs[i];
            const float4 clo = cs4[lab * 2];
            const float4 chi = cs4[lab * 2 + 1];
            float d0 = ev[i][0] - clo.x;
            float s  = d0 * d0;
            float d1 = ev[i][1] - clo.y; s = fmaf(d1, d1, s);
            float d2 = ev[i][2] - clo.z; s = fmaf(d2, d2, s);
            float d3 = ev[i][3] - clo.w; s = fmaf(d3, d3, s);
            float d4 = ev[i][4] - chi.x; s = fmaf(d4, d4, s);
            float d5 = ev[i][5] - chi.y; s = fmaf(d5, d5, s);
            float d6 = ev[i][6] - chi.z; s = fmaf(d6, d6, s);
            float d7 = ev[i][7] - chi.w; s = fmaf(d7, d7, s);
            // max(sqrt(s)-0.5,0)^2 == s - sqrt(s) + 0.25 when s > 0.25 else 0
            float val = (s - fsqrt_approx(s)) + 0.25f;
            val = (s > 0.25f) ? val : 0.f;
            vacc[t * VSLOT + lab] += val;
        }
    }

    __syncthreads();
    for (int off = T2 / 2; off > 0; off >>= 1) {
        if (t < off) {
            float* a = vacc + t * VSLOT;
            float* c = vacc + (t + off) * VSLOT;
#pragma unroll
            for (int j = 0; j < 6; j++) a[j] += c[j];
        }
        __syncthreads();
    }
    if (t >= 1 && t <= KK) atomicAdd(&g_var[b][t], vacc[t]);
}

// ---------------------------------------------------------------------------
// Finalize: cooperative smem preload of all scratch (parallel latency), then
// per-b epilogue, output write, and scratch reset for the next graph replay.
#define TF 320

__global__ void __launch_bounds__(TF) finalize_kernel(float* __restrict__ out) {
    __shared__ float sh_sums[BB][KK][DD];
    __shared__ float sh_cnt[BB][KK + 1];
    __shared__ float sh_varr[BB][KK + 1];
    __shared__ float s_var[BB], s_dist[BB], s_reg[BB], s_has[BB];
    const int t = threadIdx.x;

    if (t < BB * KK * DD) (&sh_sums[0][0][0])[t] = (&g_sums[0][0][0])[t];
    if (t < BB * (KK + 1)) {
        (&sh_cnt[0][0])[t]  = (float)(&g_cnt[0][0])[t];
        (&sh_varr[0][0])[t] = (&g_var[0][0])[t];
    }
    __syncthreads();

    if (t < BB) {
        const int b = t;
        float cnt[KK], present[KK], N = 0.f;
        float ctr[KK][DD];
#pragma unroll
        for (int k = 0; k < KK; k++) {
            cnt[k] = sh_cnt[b][k + 1];
            present[k] = cnt[k] > 0.f ? 1.f : 0.f;
            N += present[k];
            const float inv = 1.f / fmaxf(cnt[k], 1.f);
#pragma unroll
            for (int d = 0; d < DD; d++) ctr[k][d] = sh_sums[b][k][d] * inv;
        }
        float lv = 0.f;
#pragma unroll
        for (int k = 0; k < KK; k++)
            lv += present[k] * (sh_varr[b][k + 1] / fmaxf(cnt[k], 1.f));
        lv /= fmaxf(N, 1.f);

        float ld = 0.f;
        for (int i = 0; i < KK; i++) {
            for (int j = i + 1; j < KK; j++) {
                if (present[i] > 0.f && present[j] > 0.f) {
                    float dsq = 0.f;
#pragma unroll
                    for (int d = 0; d < DD; d++) {
                        float df = ctr[i][d] - ctr[j][d];
                        dsq = fmaf(df, df, dsq);
                    }
                    float dist = sqrtf(dsq);
                    float term = fmaxf(6.0f - dist, 0.f);  // 2*DELTA_D = 6
                    ld += term * term;
                }
            }
        }
        float npairs = N * (N - 1.f) * 0.5f;
        ld /= (N > 1.f) ? npairs : 1.f;

        float lr = 0.f;
#pragma unroll
        for (int k = 0; k < KK; k++) {
            if (present[k] > 0.f) {
                float nsq = 0.f;
#pragma unroll
                for (int d = 0; d < DD; d++) {
                    float c = ctr[k][d];
                    nsq = fmaf(c, c, nsq);
                }
                lr += sqrtf(nsq);
            }
        }
        lr /= fmaxf(N, 1.f);
        s_var[b] = lv; s_dist[b] = ld; s_reg[b] = lr;
        s_has[b] = (N > 0.f) ? 1.f : 0.f;
    }
    __syncthreads();
    if (t == 0) {
        float hv = 0.f, hd = 0.f, hr = 0.f, hh = 0.f;
#pragma unroll
        for (int b = 0; b < BB; b++) {
            hh += s_has[b];
            hv += s_var[b] * s_has[b];
            hd += s_dist[b] * s_has[b];
            hr += s_reg[b] * s_has[b];
        }
        const float den = fmaxf(hh, 1.f);
        const float var = hv / den, dist = hd / den, reg = hr / den;
        out[0] = var + dist + 0.001f * reg;  // ALPHA=BETA=1, GAMMA=0.001
        out[1] = var;
        out[2] = dist;
        out[3] = reg;
    }

    // reset scratch for the next graph replay
    if (t < BB * KK * DD) (&g_sums[0][0][0])[t] = 0.f;
    if (t < BB * (KK + 1)) {
        (&g_cnt[0][0])[t] = 0;
        (&g_var[0][0])[t] = 0.f;
    }
}

// ---------------------------------------------------------------------------
extern "C" void kernel_launch(void* const* d_in, const int* in_sizes, int n_in,
                              void* d_out, int out_size) {
    const float* emb  = (const float*)d_in[0];
    const int*   mask = (const int*)d_in[1];
    float*       out  = (float*)d_out;

    dim3 g1(GX1, BB);
    pass1_kernel<<<g1, T1>>>(emb, mask);
    dim3 g2(GX2, BB);
    pass2_kernel<<<g2, T2>>>(emb, mask);
    finalize_kernel<<<1, TF>>>(out);
}